// round 16
// baseline (speedup 1.0000x reference)
#include <cuda_runtime.h>

// Problem constants
#define T_LEN   4096
#define D_DIM   512
#define N_DIM   16
#define TWO_N   32
#define DQ      128            // D/4 (float4 groups per row)
#define SEG     128            // number of segments
#define L_SEG   32             // steps per segment (SEG*L_SEG == T_LEN)
#define CG      2048           // chain groups = N*D/4
#define BIG_THREADS (SEG*CG)   // 262144

typedef unsigned long long u64;

// Scratch (device globals). Layout: [CG][SEG] float4.
__device__ float4 g_b  [CG*SEG];
__device__ float4 g_sq [CG*SEG];
__device__ float4 g_hab[CG*SEG];
__device__ float4 g_hvb[CG*SEG];

__device__ __forceinline__ float sqrt_approx(float v) {
    float r;
    asm("sqrt.approx.f32 %0, %1;" : "=f"(r) : "f"(v));
    return r;
}

// ---- packed f32x2 helpers (FFMA2 path; ptxas only emits via PTX) ----
__device__ __forceinline__ u64 fma2(u64 a, u64 b, u64 c) {
    u64 d;
    asm("fma.rn.f32x2 %0, %1, %2, %3;" : "=l"(d) : "l"(a), "l"(b), "l"(c));
    return d;
}
__device__ __forceinline__ u64 mul2(u64 a, u64 b) {
    u64 d;
    asm("mul.rn.f32x2 %0, %1, %2;" : "=l"(d) : "l"(a), "l"(b));
    return d;
}
__device__ __forceinline__ u64 pack2(float lo, float hi) {
    u64 d;
    asm("mov.b64 %0, {%1, %2};" : "=l"(d) : "f"(lo), "f"(hi));
    return d;
}
__device__ __forceinline__ void unpack2(u64 v, float& lo, float& hi) {
    asm("mov.b64 {%0, %1}, %2;" : "=f"(lo), "=f"(hi) : "l"(v));
}

// ---------------------------------------------------------------------------
// K1: zero-state replay per segment -> b, Sq.  Packed f32x2 inner loop:
// 8 scalar chains = 4 u64 pairs; 4 packed instrs per pair per step
// (2 instr/chain-step vs 4 scalar).  x float4 reinterpreted as 2 pairs free.
// Threads: SEG * 8 * DQ = 131072; 32 steps each.
// ---------------------------------------------------------------------------
__global__ void k_b(const ulonglong2* __restrict__ xu, const float4* __restrict__ a4p) {
    int tid = blockIdx.x * blockDim.x + threadIdx.x;
    int s   = tid >> 10;           // segment 0..127
    int r   = tid & 1023;
    int np  = r >> 7;              // n-pair 0..7 (covers n = np*2, np*2+1)
    int g   = r & (DQ - 1);

    u64 a2[4], om2[4], q2[4], Sq2[4];
    #pragma unroll
    for (int j = 0; j < 2; j++) {
        float4 av = a4p[(np * 2 + j) * DQ + g];
        a2 [j*2+0] = pack2(av.x, av.y);
        a2 [j*2+1] = pack2(av.z, av.w);
        om2[j*2+0] = pack2(1.f - av.x, 1.f - av.y);
        om2[j*2+1] = pack2(1.f - av.z, 1.f - av.w);
    }
    #pragma unroll
    for (int k = 0; k < 4; k++) { q2[k] = 0ULL; Sq2[k] = 0ULL; }
    u64 neg1 = pack2(-1.f, -1.f);

    const ulonglong2* xp = xu + (size_t)(s * L_SEG) * DQ + g;

    #pragma unroll 4
    for (int i = 0; i < L_SEG; i++) {
        ulonglong2 xv = xp[(size_t)i * DQ];
        u64 xh[2] = {xv.x, xv.y};
        #pragma unroll
        for (int k = 0; k < 4; k++) {
            u64 x2 = xh[k & 1];
            u64 d2 = fma2(neg1, q2[k], x2);     // x - q (bit-exact)
            u64 dd = mul2(d2, d2);
            Sq2[k] = fma2(om2[k], Sq2[k], dd);
            q2[k]  = fma2(a2[k], d2, q2[k]);
        }
    }
    #pragma unroll
    for (int j = 0; j < 2; j++) {
        int cg = (np * 2 + j) * DQ + g;
        *reinterpret_cast<ulonglong2*>(&g_b [cg * SEG + s]) =
            make_ulonglong2(q2[j*2], q2[j*2+1]);
        *reinterpret_cast<ulonglong2*>(&g_sq[cg * SEG + s]) =
            make_ulonglong2(Sq2[j*2], Sq2[j*2+1]);
    }
}

// ---------------------------------------------------------------------------
// K2: combined warp scan over 128 segments, 4 segments per lane. (R15 config)
// hv forcing: f = a*om*Sq - 2*H*P*b + H^2*P*(1-P)   (Sd-free form)
// ---------------------------------------------------------------------------
__global__ void k_scan2(const float4* __restrict__ ha0,
                        const float4* __restrict__ hs0,
                        const float4* __restrict__ a4p) {
    int cg   = (blockIdx.x * blockDim.x + threadIdx.x) >> 5;
    int lane = threadIdx.x & 31;

    float4 av = a4p[cg];
    float al[4] = {av.x, av.y, av.z, av.w};
    float om[4], P[4];
    #pragma unroll
    for (int j = 0; j < 4; j++) { om[j] = 1.f - al[j]; P[j] = om[j]; }
    #pragma unroll
    for (int k = 0; k < 5; k++) {
        #pragma unroll
        for (int j = 0; j < 4; j++) P[j] *= P[j];   // (1-a)^32
    }

    float b[4][4], sq[4][4];
    #pragma unroll
    for (int m = 0; m < 4; m++) {
        float4 bv  = g_b [cg * SEG + 4 * lane + m];
        float4 sqv = g_sq[cg * SEG + 4 * lane + m];
        b [m][0] = bv.x;  b [m][1] = bv.y;  b [m][2] = bv.z;  b [m][3] = bv.w;
        sq[m][0] = sqv.x; sq[m][1] = sqv.y; sq[m][2] = sqv.z; sq[m][3] = sqv.w;
    }

    // ---------- scan 1: ha ----------
    float A[4], Q[4], pw[4], qs[5][4];
    #pragma unroll
    for (int j = 0; j < 4; j++) {
        float t = fmaf(P[j], b[0][j], b[1][j]);
        t = fmaf(P[j], t, b[2][j]);
        A[j] = fmaf(P[j], t, b[3][j]);
        float p2 = P[j] * P[j];
        Q[j]  = p2 * p2;
        pw[j] = Q[j];
    }
    #pragma unroll
    for (int step = 0; step < 5; step++) {
        int off = 1 << step;
        float t[4];
        #pragma unroll
        for (int j = 0; j < 4; j++) {
            qs[step][j] = pw[j];
            t[j] = __shfl_up_sync(0xFFFFFFFFu, A[j], off);
        }
        if (lane >= off) {
            #pragma unroll
            for (int j = 0; j < 4; j++) A[j] = fmaf(pw[j], t[j], A[j]);
        }
        #pragma unroll
        for (int j = 0; j < 4; j++) pw[j] *= pw[j];
    }
    float Ql[4] = {1.f, 1.f, 1.f, 1.f};
    #pragma unroll
    for (int bit = 0; bit < 5; bit++) {
        if (lane & (1 << bit)) {
            #pragma unroll
            for (int j = 0; j < 4; j++) Ql[j] *= qs[bit][j];
        }
    }
    float excl[4];
    #pragma unroll
    for (int j = 0; j < 4; j++) {
        excl[j] = __shfl_up_sync(0xFFFFFFFFu, A[j], 1);
        if (lane == 0) excl[j] = 0.f;
    }
    float4 h0v = ha0[cg];
    float h0[4] = {h0v.x, h0v.y, h0v.z, h0v.w};
    float Ha[4][4];
    #pragma unroll
    for (int j = 0; j < 4; j++) {
        Ha[0][j] = fmaf(Ql[j], h0[j], excl[j]);
        Ha[1][j] = fmaf(P[j], Ha[0][j], b[0][j]);
        Ha[2][j] = fmaf(P[j], Ha[1][j], b[1][j]);
        Ha[3][j] = fmaf(P[j], Ha[2][j], b[2][j]);
    }
    #pragma unroll
    for (int m = 0; m < 4; m++)
        g_hab[cg * SEG + 4 * lane + m] =
            make_float4(Ha[m][0], Ha[m][1], Ha[m][2], Ha[m][3]);

    // ---------- build hv forcing (Sd-free) ----------
    float f[4][4];
    #pragma unroll
    for (int j = 0; j < 4; j++) {
        float aom = al[j] * om[j];
        float p1p = P[j] * (1.f - P[j]);
        #pragma unroll
        for (int m = 0; m < 4; m++) {
            float H = Ha[m][j];
            f[m][j] = aom * sq[m][j] - 2.f * H * P[j] * b[m][j] + H * H * p1p;
        }
    }

    // ---------- scan 2: hv ----------
    float B[4];
    #pragma unroll
    for (int j = 0; j < 4; j++) {
        float t = fmaf(P[j], f[0][j], f[1][j]);
        t = fmaf(P[j], t, f[2][j]);
        B[j] = fmaf(P[j], t, f[3][j]);
    }
    #pragma unroll
    for (int step = 0; step < 5; step++) {
        int off = 1 << step;
        float t[4];
        #pragma unroll
        for (int j = 0; j < 4; j++) t[j] = __shfl_up_sync(0xFFFFFFFFu, B[j], off);
        if (lane >= off) {
            #pragma unroll
            for (int j = 0; j < 4; j++) B[j] = fmaf(qs[step][j], t[j], B[j]);
        }
    }
    float excl2[4];
    #pragma unroll
    for (int j = 0; j < 4; j++) {
        excl2[j] = __shfl_up_sync(0xFFFFFFFFu, B[j], 1);
        if (lane == 0) excl2[j] = 0.f;
    }
    float4 hsv = hs0[cg];
    float v0[4] = {hsv.x * hsv.x, hsv.y * hsv.y, hsv.z * hsv.z, hsv.w * hsv.w};
    float Hv[4][4];
    #pragma unroll
    for (int j = 0; j < 4; j++) {
        Hv[0][j] = fmaxf(fmaf(Ql[j], v0[j], excl2[j]), 0.f);
        Hv[1][j] = fmaxf(fmaf(P[j], Hv[0][j], f[0][j]), 0.f);
        Hv[2][j] = fmaxf(fmaf(P[j], Hv[1][j], f[1][j]), 0.f);
        Hv[3][j] = fmaxf(fmaf(P[j], Hv[2][j], f[2][j]), 0.f);
    }
    #pragma unroll
    for (int m = 0; m < 4; m++)
        g_hvb[cg * SEG + 4 * lane + m] =
            make_float4(Hv[m][0], Hv[m][1], Hv[m][2], Hv[m][3]);
}

// ---------------------------------------------------------------------------
// K3: fused writer (R9 shape: 1 cg/thread, 262144 threads), packed f32x2
// recurrences; ha stored directly as v2.b64 streaming store.
// ---------------------------------------------------------------------------
__global__ void k_out(const ulonglong2* __restrict__ xu, const float4* __restrict__ a4p,
                      float4* __restrict__ out4) {
    int tid = blockIdx.x * blockDim.x + threadIdx.x;
    int s  = tid >> 11;          // segment 0..127
    int cg = tid & (CG - 1);
    int n  = cg >> 7;
    int g  = cg & (DQ - 1);

    float4 a = a4p[cg];
    u64 a2[2]  = {pack2(a.x, a.y), pack2(a.z, a.w)};
    u64 om2[2] = {pack2(1.f - a.x, 1.f - a.y), pack2(1.f - a.z, 1.f - a.w)};
    u64 neg1 = pack2(-1.f, -1.f);

    ulonglong2 hab = *reinterpret_cast<const ulonglong2*>(&g_hab[cg * SEG + s]);
    ulonglong2 hvb = *reinterpret_cast<const ulonglong2*>(&g_hvb[cg * SEG + s]);
    u64 ha2[2] = {hab.x, hab.y};
    u64 hv2[2] = {hvb.x, hvb.y};
    int t0 = s * L_SEG;

    #pragma unroll 4
    for (int i = 0; i < L_SEG; i++) {
        int t = t0 + i;
        ulonglong2 xv = xu[(size_t)t * DQ + g];
        u64 xh[2] = {xv.x, xv.y};
        #pragma unroll
        for (int h = 0; h < 2; h++) {
            u64 u2 = fma2(neg1, ha2[h], xh[h]);   // x - ha
            u64 uu = mul2(u2, u2);
            u64 tt = fma2(a2[h], uu, hv2[h]);
            hv2[h] = mul2(om2[h], tt);
            ha2[h] = fma2(a2[h], u2, ha2[h]);
        }
        size_t row = (size_t)t * TWO_N;

        // streaming store of ha pair directly (no unpack)
        float4* pa = &out4[(row + n) * DQ + g];
        asm volatile("st.global.cs.v2.b64 [%0], {%1, %2};"
                     :: "l"(pa), "l"(ha2[0]), "l"(ha2[1]) : "memory");

        // hv: unpack for MUFU sqrt, then streaming store
        float v0, v1, v2, v3;
        unpack2(hv2[0], v0, v1);
        unpack2(hv2[1], v2, v3);
        __stcs(&out4[(row + N_DIM + n) * DQ + g],
               make_float4(sqrt_approx(v0), sqrt_approx(v1),
                           sqrt_approx(v2), sqrt_approx(v3)));
    }

    if (s == SEG - 1) {
        const size_t base = (size_t)T_LEN * TWO_N * DQ;   // float4 units
        float a0, a1, a2f, a3;
        unpack2(ha2[0], a0, a1);
        unpack2(ha2[1], a2f, a3);
        out4[base + cg] = make_float4(a0, a1, a2f, a3);
        float v0, v1, v2, v3;
        unpack2(hv2[0], v0, v1);
        unpack2(hv2[1], v2, v3);
        out4[base + CG + cg] =
            make_float4(sqrt_approx(v0), sqrt_approx(v1),
                        sqrt_approx(v2), sqrt_approx(v3));
    }
}

// ---------------------------------------------------------------------------
extern "C" void kernel_launch(void* const* d_in, const int* in_sizes, int n_in,
                              void* d_out, int out_size) {
    const ulonglong2* xu = (const ulonglong2*)d_in[0];   // [T, D] as packed pairs
    const float4* ha0 = (const float4*)d_in[1];          // [N, D]
    const float4* hs0 = (const float4*)d_in[2];          // [N, D]
    const float4* a4  = (const float4*)d_in[3];          // [N, D]
    float4* out4 = (float4*)d_out;

    k_b    <<<(SEG * 8 * DQ) / 256, 256>>>(xu, a4);
    k_scan2<<<(CG * 32) / 256, 256>>>(ha0, hs0, a4);
    k_out  <<<BIG_THREADS / 256, 256>>>(xu, a4, out4);
}

// round 17
// speedup vs baseline: 1.0392x; 1.0392x over previous
#include <cuda_runtime.h>

// Problem constants
#define T_LEN   4096
#define D_DIM   512
#define N_DIM   16
#define TWO_N   32
#define DQ      128            // D/4 (float4 groups per row)
#define SEG     128            // number of segments
#define L_SEG   32             // steps per segment (SEG*L_SEG == T_LEN)
#define CG      2048           // chain groups = N*D/4
#define BIG_THREADS (SEG*CG)   // 262144

typedef unsigned long long u64;

// Scratch (device globals). Layout: [CG][SEG] float4.
__device__ float4 g_b  [CG*SEG];
__device__ float4 g_sq [CG*SEG];
__device__ float4 g_hab[CG*SEG];
__device__ float4 g_hvb[CG*SEG];

__device__ __forceinline__ float sqrt_approx(float v) {
    float r;
    asm("sqrt.approx.f32 %0, %1;" : "=f"(r) : "f"(v));
    return r;
}

// ---- packed f32x2 helpers ----
__device__ __forceinline__ u64 fma2(u64 a, u64 b, u64 c) {
    u64 d;
    asm("fma.rn.f32x2 %0, %1, %2, %3;" : "=l"(d) : "l"(a), "l"(b), "l"(c));
    return d;
}
__device__ __forceinline__ u64 mul2(u64 a, u64 b) {
    u64 d;
    asm("mul.rn.f32x2 %0, %1, %2;" : "=l"(d) : "l"(a), "l"(b));
    return d;
}
__device__ __forceinline__ u64 pack2(float lo, float hi) {
    u64 d;
    asm("mov.b64 %0, {%1, %2};" : "=l"(d) : "f"(lo), "f"(hi));
    return d;
}

// ---------------------------------------------------------------------------
// K1: zero-state replay per segment -> b, Sq.  Packed f32x2 (R16-proven:
// 13.1 us).  8 scalar chains = 4 u64 pairs; 2 instr/chain-step.
// Threads: SEG * 8 * DQ = 131072; 32 steps each.
// ---------------------------------------------------------------------------
__global__ void k_b(const ulonglong2* __restrict__ xu, const float4* __restrict__ a4p) {
    int tid = blockIdx.x * blockDim.x + threadIdx.x;
    int s   = tid >> 10;           // segment 0..127
    int r   = tid & 1023;
    int np  = r >> 7;              // n-pair 0..7 (covers n = np*2, np*2+1)
    int g   = r & (DQ - 1);

    u64 a2[4], om2[4], q2[4], Sq2[4];
    #pragma unroll
    for (int j = 0; j < 2; j++) {
        float4 av = a4p[(np * 2 + j) * DQ + g];
        a2 [j*2+0] = pack2(av.x, av.y);
        a2 [j*2+1] = pack2(av.z, av.w);
        om2[j*2+0] = pack2(1.f - av.x, 1.f - av.y);
        om2[j*2+1] = pack2(1.f - av.z, 1.f - av.w);
    }
    #pragma unroll
    for (int k = 0; k < 4; k++) { q2[k] = 0ULL; Sq2[k] = 0ULL; }
    u64 neg1 = pack2(-1.f, -1.f);

    const ulonglong2* xp = xu + (size_t)(s * L_SEG) * DQ + g;

    #pragma unroll 4
    for (int i = 0; i < L_SEG; i++) {
        ulonglong2 xv = xp[(size_t)i * DQ];
        u64 xh[2] = {xv.x, xv.y};
        #pragma unroll
        for (int k = 0; k < 4; k++) {
            u64 x2 = xh[k & 1];
            u64 d2 = fma2(neg1, q2[k], x2);     // x - q (bit-exact)
            u64 dd = mul2(d2, d2);
            Sq2[k] = fma2(om2[k], Sq2[k], dd);
            q2[k]  = fma2(a2[k], d2, q2[k]);
        }
    }
    #pragma unroll
    for (int j = 0; j < 2; j++) {
        int cg = (np * 2 + j) * DQ + g;
        *reinterpret_cast<ulonglong2*>(&g_b [cg * SEG + s]) =
            make_ulonglong2(q2[j*2], q2[j*2+1]);
        *reinterpret_cast<ulonglong2*>(&g_sq[cg * SEG + s]) =
            make_ulonglong2(Sq2[j*2], Sq2[j*2+1]);
    }
}

// ---------------------------------------------------------------------------
// K2: combined warp scan over 128 segments, 4 segments per lane.
// hv forcing: f = a*om*Sq - 2*H*P*b + H^2*P*(1-P)   (Sd-free form)
// ---------------------------------------------------------------------------
__global__ void k_scan2(const float4* __restrict__ ha0,
                        const float4* __restrict__ hs0,
                        const float4* __restrict__ a4p) {
    int cg   = (blockIdx.x * blockDim.x + threadIdx.x) >> 5;
    int lane = threadIdx.x & 31;

    float4 av = a4p[cg];
    float al[4] = {av.x, av.y, av.z, av.w};
    float om[4], P[4];
    #pragma unroll
    for (int j = 0; j < 4; j++) { om[j] = 1.f - al[j]; P[j] = om[j]; }
    #pragma unroll
    for (int k = 0; k < 5; k++) {
        #pragma unroll
        for (int j = 0; j < 4; j++) P[j] *= P[j];   // (1-a)^32
    }

    float b[4][4], sq[4][4];
    #pragma unroll
    for (int m = 0; m < 4; m++) {
        float4 bv  = g_b [cg * SEG + 4 * lane + m];
        float4 sqv = g_sq[cg * SEG + 4 * lane + m];
        b [m][0] = bv.x;  b [m][1] = bv.y;  b [m][2] = bv.z;  b [m][3] = bv.w;
        sq[m][0] = sqv.x; sq[m][1] = sqv.y; sq[m][2] = sqv.z; sq[m][3] = sqv.w;
    }

    // ---------- scan 1: ha ----------
    float A[4], Q[4], pw[4], qs[5][4];
    #pragma unroll
    for (int j = 0; j < 4; j++) {
        float t = fmaf(P[j], b[0][j], b[1][j]);
        t = fmaf(P[j], t, b[2][j]);
        A[j] = fmaf(P[j], t, b[3][j]);
        float p2 = P[j] * P[j];
        Q[j]  = p2 * p2;
        pw[j] = Q[j];
    }
    #pragma unroll
    for (int step = 0; step < 5; step++) {
        int off = 1 << step;
        float t[4];
        #pragma unroll
        for (int j = 0; j < 4; j++) {
            qs[step][j] = pw[j];
            t[j] = __shfl_up_sync(0xFFFFFFFFu, A[j], off);
        }
        if (lane >= off) {
            #pragma unroll
            for (int j = 0; j < 4; j++) A[j] = fmaf(pw[j], t[j], A[j]);
        }
        #pragma unroll
        for (int j = 0; j < 4; j++) pw[j] *= pw[j];
    }
    float Ql[4] = {1.f, 1.f, 1.f, 1.f};
    #pragma unroll
    for (int bit = 0; bit < 5; bit++) {
        if (lane & (1 << bit)) {
            #pragma unroll
            for (int j = 0; j < 4; j++) Ql[j] *= qs[bit][j];
        }
    }
    float excl[4];
    #pragma unroll
    for (int j = 0; j < 4; j++) {
        excl[j] = __shfl_up_sync(0xFFFFFFFFu, A[j], 1);
        if (lane == 0) excl[j] = 0.f;
    }
    float4 h0v = ha0[cg];
    float h0[4] = {h0v.x, h0v.y, h0v.z, h0v.w};
    float Ha[4][4];
    #pragma unroll
    for (int j = 0; j < 4; j++) {
        Ha[0][j] = fmaf(Ql[j], h0[j], excl[j]);
        Ha[1][j] = fmaf(P[j], Ha[0][j], b[0][j]);
        Ha[2][j] = fmaf(P[j], Ha[1][j], b[1][j]);
        Ha[3][j] = fmaf(P[j], Ha[2][j], b[2][j]);
    }
    #pragma unroll
    for (int m = 0; m < 4; m++)
        g_hab[cg * SEG + 4 * lane + m] =
            make_float4(Ha[m][0], Ha[m][1], Ha[m][2], Ha[m][3]);

    // ---------- build hv forcing (Sd-free) ----------
    float f[4][4];
    #pragma unroll
    for (int j = 0; j < 4; j++) {
        float aom = al[j] * om[j];
        float p1p = P[j] * (1.f - P[j]);
        #pragma unroll
        for (int m = 0; m < 4; m++) {
            float H = Ha[m][j];
            f[m][j] = aom * sq[m][j] - 2.f * H * P[j] * b[m][j] + H * H * p1p;
        }
    }

    // ---------- scan 2: hv ----------
    float B[4];
    #pragma unroll
    for (int j = 0; j < 4; j++) {
        float t = fmaf(P[j], f[0][j], f[1][j]);
        t = fmaf(P[j], t, f[2][j]);
        B[j] = fmaf(P[j], t, f[3][j]);
    }
    #pragma unroll
    for (int step = 0; step < 5; step++) {
        int off = 1 << step;
        float t[4];
        #pragma unroll
        for (int j = 0; j < 4; j++) t[j] = __shfl_up_sync(0xFFFFFFFFu, B[j], off);
        if (lane >= off) {
            #pragma unroll
            for (int j = 0; j < 4; j++) B[j] = fmaf(qs[step][j], t[j], B[j]);
        }
    }
    float excl2[4];
    #pragma unroll
    for (int j = 0; j < 4; j++) {
        excl2[j] = __shfl_up_sync(0xFFFFFFFFu, B[j], 1);
        if (lane == 0) excl2[j] = 0.f;
    }
    float4 hsv = hs0[cg];
    float v0[4] = {hsv.x * hsv.x, hsv.y * hsv.y, hsv.z * hsv.z, hsv.w * hsv.w};
    float Hv[4][4];
    #pragma unroll
    for (int j = 0; j < 4; j++) {
        Hv[0][j] = fmaxf(fmaf(Ql[j], v0[j], excl2[j]), 0.f);
        Hv[1][j] = fmaxf(fmaf(P[j], Hv[0][j], f[0][j]), 0.f);
        Hv[2][j] = fmaxf(fmaf(P[j], Hv[1][j], f[1][j]), 0.f);
        Hv[3][j] = fmaxf(fmaf(P[j], Hv[2][j], f[2][j]), 0.f);
    }
    #pragma unroll
    for (int m = 0; m < 4; m++)
        g_hvb[cg * SEG + 4 * lane + m] =
            make_float4(Hv[m][0], Hv[m][1], Hv[m][2], Hv[m][3]);
}

// ---------------------------------------------------------------------------
// K3: fused writer — R15 scalar form (proven ~40 us), float4 STG.128 .cs.
// 1 cg/thread, 262144 threads.  Unroll 8 for extra store MLP.
// ---------------------------------------------------------------------------
__global__ void k_out(const float4* __restrict__ x4, const float4* __restrict__ a4p,
                      float4* __restrict__ out4) {
    int tid = blockIdx.x * blockDim.x + threadIdx.x;
    int s  = tid >> 11;          // segment 0..127
    int cg = tid & (CG - 1);
    int n  = cg >> 7;
    int g  = cg & (DQ - 1);

    float4 a = a4p[cg];
    float omx = 1.f - a.x, omy = 1.f - a.y, omz = 1.f - a.z, omw = 1.f - a.w;

    float4 ha = g_hab[cg * SEG + s];
    float4 hv = g_hvb[cg * SEG + s];
    int t0 = s * L_SEG;

    #pragma unroll 8
    for (int i = 0; i < L_SEG; i++) {
        int t = t0 + i;
        float4 xv = x4[(size_t)t * DQ + g];
        float ux = xv.x - ha.x, uy = xv.y - ha.y, uz = xv.z - ha.z, uw = xv.w - ha.w;
        hv.x = omx * fmaf(a.x, ux * ux, hv.x);
        hv.y = omy * fmaf(a.y, uy * uy, hv.y);
        hv.z = omz * fmaf(a.z, uz * uz, hv.z);
        hv.w = omw * fmaf(a.w, uw * uw, hv.w);
        ha.x = fmaf(a.x, ux, ha.x);
        ha.y = fmaf(a.y, uy, ha.y);
        ha.z = fmaf(a.z, uz, ha.z);
        ha.w = fmaf(a.w, uw, ha.w);
        size_t row = (size_t)t * TWO_N;
        __stcs(&out4[(row + n) * DQ + g], ha);
        __stcs(&out4[(row + N_DIM + n) * DQ + g],
               make_float4(sqrt_approx(hv.x), sqrt_approx(hv.y),
                           sqrt_approx(hv.z), sqrt_approx(hv.w)));
    }

    if (s == SEG - 1) {
        const size_t base = (size_t)T_LEN * TWO_N * DQ;   // float4 units
        out4[base + cg] = ha;
        out4[base + CG + cg] =
            make_float4(sqrt_approx(hv.x), sqrt_approx(hv.y),
                        sqrt_approx(hv.z), sqrt_approx(hv.w));
    }
}

// ---------------------------------------------------------------------------
extern "C" void kernel_launch(void* const* d_in, const int* in_sizes, int n_in,
                              void* d_out, int out_size) {
    const ulonglong2* xu = (const ulonglong2*)d_in[0];   // [T, D] packed pairs
    const float4* x4  = (const float4*)d_in[0];          // [T, D]
    const float4* ha0 = (const float4*)d_in[1];          // [N, D]
    const float4* hs0 = (const float4*)d_in[2];          // [N, D]
    const float4* a4  = (const float4*)d_in[3];          // [N, D]
    float4* out4 = (float4*)d_out;

    k_b    <<<(SEG * 8 * DQ) / 256, 256>>>(xu, a4);
    k_scan2<<<(CG * 32) / 256, 256>>>(ha0, hs0, a4);
    k_out  <<<BIG_THREADS / 256, 256>>>(x4, a4, out4);
}